// round 16
// baseline (speedup 1.0000x reference)
#include <cuda_runtime.h>
#include <math.h>
#include <stdint.h>

// RandomizedOscillatorsNetwork: B=128, T=1024, I=64, H=512
// 16 clusters x 8 CTAs; cluster owns 8 batch rows; CTA owns 64 H-cols, weight slice
// (h2h||x2h) [576x64] resident in SMEM.
// R16: warp-specialized DUAL-STREAM pipeline. Warps 0-3 = stream A (batches 0-3),
// warps 4-7 = stream B (batches 4-7). Each stream: private vb[2][576][4], private
// mbarrier PAIR (armed a phase ahead), private partials, named-barrier group sync.
// No __syncthreads in the loop: while one stream spins on its exchange, the other
// stream's GEMM keeps the fma pipe busy on the same SMSP.
// Exchange: 1KB DSMEM engine push per CTA per stream, 7 lanes push in parallel.

#define DTc 0.042f
#define Bn 128
#define Tn 1024
#define In 64
#define Hn 512
#define NT 256

#define W_BYTES   147456                  // [576][64] f32
#define VBA_OFF   147456                  // vbA[2][576][4] f32 (rows 0..511 hy, 512..575 x)
#define VBB_OFF   165888                  // vbB[2][576][4]
#define RFA_OFF   184320                  // rfA[2][4 warps][4 b][64 col]
#define RFB_OFF   192512
#define MB_OFF    200704                  // 4 mbarriers: A0,A1,B0,B1 (8B each)
#define SMEM_BYTES 200768

#define VB_STRIDE_F 2304                  // floats per vb buffer (576*4)
#define VB_BUF_BYTES 9216
#define SLICE_BYTES 1024                  // 64 rows x 4 batches x 4B
#define STEP_TX 7168                      // 7 peer slices per phase

typedef unsigned long long u64;

__device__ __forceinline__ u64 pack2(float lo, float hi) {
    u64 r; asm("mov.b64 %0, {%1, %2};" : "=l"(r) : "f"(lo), "f"(hi)); return r;
}
__device__ __forceinline__ void unpack2(u64 v, float& lo, float& hi) {
    asm("mov.b64 {%0, %1}, %2;" : "=f"(lo), "=f"(hi) : "l"(v));
}
__device__ __forceinline__ u64 ffma2(u64 a, u64 b, u64 c) {
    u64 d; asm("fma.rn.f32x2 %0, %1, %2, %3;" : "=l"(d) : "l"(a), "l"(b), "l"(c)); return d;
}
__device__ __forceinline__ float tanh_fast(float v) {
    float r; asm("tanh.approx.f32 %0, %1;" : "=f"(r) : "f"(v)); return r;
}
__device__ __forceinline__ uint32_t smem_u32(const void* p) {
    uint32_t a; asm("{ .reg .u64 t; cvta.to.shared.u64 t, %1; cvt.u32.u64 %0, t; }"
                    : "=r"(a) : "l"(p)); return a;
}
__device__ __forceinline__ uint32_t mapa_u32(uint32_t addr, int rank) {
    uint32_t r; asm("mapa.shared::cluster.u32 %0, %1, %2;" : "=r"(r) : "r"(addr), "r"(rank));
    return r;
}
__device__ __forceinline__ void mbar_init(uint32_t mbar, uint32_t cnt) {
    asm volatile("mbarrier.init.shared.b64 [%0], %1;" :: "r"(mbar), "r"(cnt) : "memory");
}
__device__ __forceinline__ void mbar_expect(uint32_t mbar, uint32_t tx) {
    asm volatile("mbarrier.arrive.expect_tx.shared.b64 _, [%0], %1;" :: "r"(mbar), "r"(tx) : "memory");
}
__device__ __forceinline__ void mbar_wait(uint32_t mbar, uint32_t parity) {
    asm volatile(
        "{\n\t.reg .pred P1;\n"
        "W_%=:\n\t"
        "mbarrier.try_wait.parity.acquire.cta.shared::cta.b64 P1, [%0], %1, 0x989680;\n\t"
        "@P1 bra.uni D_%=;\n\t"
        "bra.uni W_%=;\n"
        "D_%=:\n\t}"
        :: "r"(mbar), "r"(parity) : "memory");
}
__device__ __forceinline__ void dsmem_push(uint32_t dst, uint32_t src, uint32_t bytes, uint32_t rmbar) {
    asm volatile(
        "cp.async.bulk.shared::cluster.shared::cta.mbarrier::complete_tx::bytes [%0], [%1], %2, [%3];"
        :: "r"(dst), "r"(src), "r"(bytes), "r"(rmbar) : "memory");
}

__global__ __launch_bounds__(NT, 1) __cluster_dims__(8, 1, 1)
void ron_kernel(const float* __restrict__ x, const float* __restrict__ x2h,
                const float* __restrict__ h2h, const float* __restrict__ bias,
                const float* __restrict__ gam, const float* __restrict__ eps,
                float* __restrict__ out, long long out_elems)
{
    extern __shared__ char smem[];
    float* W = (float*)smem;
    const uint32_t sbase = smem_u32(smem);

    const int tid  = threadIdx.x;
    const int cl   = blockIdx.x >> 3;
    const int rank = blockIdx.x & 7;
    const int c0   = rank * 64;
    const int b0   = cl * 8;

    const int wid  = tid >> 5;
    const int g    = wid >> 2;            // stream 0 (A) / 1 (B)
    const int ga   = wid & 3;             // warp within stream
    const int gtid = tid & 127;           // thread within stream
    const int cg   = tid & 31;

    // stream-local bases
    const int vbOff = g ? VBB_OFF : VBA_OFF;
    float* vbS = (float*)(smem + vbOff);            // [2][576][4]
    float* rfS = (float*)(smem + (g ? RFB_OFF : RFA_OFF)); // [2][4][4][64]
    const uint32_t mb0 = sbase + MB_OFF + g*16;     // mbar pair for this stream
    const uint32_t mb1 = mb0 + 8;
    const int barid = 1 + g;

    // prologue: resident weight slice W[k][j]
    for (int idx = tid; idx < 576*64; idx += NT) {
        int k = idx >> 6, j = idx & 63;
        W[idx] = (k < Hn) ? h2h[(size_t)k*Hn + c0 + j] : x2h[(size_t)(k - Hn)*Hn + c0 + j];
    }
    // zero bootstrap buffers (buf 1) of both streams
    for (int idx = tid; idx < 2*VB_STRIDE_F; idx += NT) {
        ((float*)(smem + VBA_OFF))[VB_STRIDE_F + 0] = ((float*)(smem + VBA_OFF))[VB_STRIDE_F + 0]; // no-op guard
        ((float*)(smem + VBA_OFF + VB_BUF_BYTES))[idx % VB_STRIDE_F] = 0.f;
        ((float*)(smem + VBB_OFF + VB_BUF_BYTES))[idx % VB_STRIDE_F] = 0.f;
    }
    __syncthreads();

    // epilogue mapping: thread owns (col, batch bh) and (col, batch bh+2) of its stream
    const int col = gtid & 63, bh = gtid >> 6;      // bh in 0..1
    const int hg  = c0 + col;
    const float bia = bias[hg], ga_ = gam[hg], ep = eps[hg];
    float hyP = 0.f, hzP = 0.f, hyQ = 0.f, hzQ = 0.f;

    // x pointers (global batches b0 + 4g + bh, b0 + 4g + bh + 2)
    const float* xpP = x + ((size_t)(b0 + 4*g + bh)     * Tn) * In + col;
    const float* xpQ = x + ((size_t)(b0 + 4*g + bh + 2) * Tn) * In + col;

    // stage x(0) into buf 1 x-rows
    {
        float* vx = vbS + VB_STRIDE_F + (512 + col)*4;
        vx[bh]     = xpP[0];
        vx[bh + 2] = xpQ[0];
    }
    if (tid == 0) {
        mbar_init(sbase + MB_OFF +  0, 1);
        mbar_init(sbase + MB_OFF +  8, 1);
        mbar_init(sbase + MB_OFF + 16, 1);
        mbar_init(sbase + MB_OFF + 24, 1);
    }
    __syncthreads();
    if (tid == 0) {   // arm BOTH phases of both streams ahead of any push
        mbar_expect(sbase + MB_OFF +  0, STEP_TX);
        mbar_expect(sbase + MB_OFF +  8, STEP_TX);
        mbar_expect(sbase + MB_OFF + 16, STEP_TX);
        mbar_expect(sbase + MB_OFF + 24, STEP_TX);
    }
    asm volatile("barrier.cluster.arrive.aligned;" ::: "memory");
    asm volatile("barrier.cluster.wait.aligned;"   ::: "memory");

    // GEMM pointers: warp ga owns k-rows [144*ga, 144*ga+144), lane owns cols {2cg,2cg+1}
    const float* Wr0 = W + (ga*144)*64 + cg*2;

    // pusher precompute: lanes gtid<7 of warp ga==0 push to rank+1+gtid
    uint32_t dstV = 0, dstM0 = 0, dstM1 = 0;
    if (gtid < 7) {
        int dr = (rank + 1 + gtid) & 7;
        dstV  = mapa_u32(sbase + vbOff, dr);
        dstM0 = mapa_u32(mb0, dr);
        dstM1 = mapa_u32(mb1, dr);
    }

    int ph0 = 0, ph1 = 0;   // per-mbar phase parity

    const size_t BTH = (size_t)Bn * Tn * Hn;
    const bool writeFinal = (out_elems >= (long long)(BTH + (size_t)Bn * Hn));

    for (int t = 0; t < Tn; t++) {
        const int prev = (t - 1) & 1, cur = t & 1;
        const int tn = (t + 1 < Tn) ? (t + 1) : t;
        const float xnP = xpP[(size_t)tn * In];     // prefetch x(t+1)
        const float xnQ = xpQ[(size_t)tn * In];

        if (t > 0) {
            // wait for the 7 peer slices of this stream's phase (t-1)
            if (prev == 0) { mbar_wait(mb0, ph0); if (gtid == 0) mbar_expect(mb0, STEP_TX); }
            else           { mbar_wait(mb1, ph1); if (gtid == 0) mbar_expect(mb1, STEP_TX); }
            if (gtid == 0) {}  // (rearm done above, 2-step margin before reuse)
            if (prev == 0) ph0 ^= 1; else ph1 ^= 1;
        }

        // ---- GEMM: 144 contiguous k-rows, 2 cols x 4 batches per lane
        u64 a00=0ull,a01=0ull,a10=0ull,a11=0ull;
        {
            const float* Wr = Wr0;
            const float* vr = vbS + prev*VB_STRIDE_F + (ga*144)*4;
            #pragma unroll 8
            for (int kk = 0; kk < 144; kk++) {
                float2 wv = *(const float2*)(Wr + kk*64);               // LDS.64 per-lane
                ulonglong2 hv = *(const ulonglong2*)(vr + kk*4);        // LDS.128 broadcast
                u64 w0 = pack2(wv.x, wv.x), w1 = pack2(wv.y, wv.y);
                a00 = ffma2(hv.x, w0, a00); a01 = ffma2(hv.x, w1, a01);
                a10 = ffma2(hv.y, w0, a10); a11 = ffma2(hv.y, w1, a11);
            }
        }

        // ---- stage split-K partials rfS[cur][ga][b][col]
        {
            float* rw = rfS + cur*1024 + ga*256 + cg*2;
            float l0,h0,l1,h1;
            unpack2(a00,l0,h0); unpack2(a01,l1,h1);
            *(float2*)(rw +   0) = make_float2(l0,l1);   // batch 0
            *(float2*)(rw +  64) = make_float2(h0,h1);   // batch 1
            unpack2(a10,l0,h0); unpack2(a11,l1,h1);
            *(float2*)(rw + 128) = make_float2(l0,l1);   // batch 2
            *(float2*)(rw + 192) = make_float2(h0,h1);   // batch 3
        }
        asm volatile("bar.sync %0, 128;" :: "r"(barid) : "memory");

        // ---- reduce + oscillator update (2 outputs per thread)
        {
            const float* r0 = rfS + cur*1024 + bh*64 + col;
            const float* r1 = r0 + 128;
            float s0 = 0.f, s1 = 0.f;
            #pragma unroll
            for (int q = 0; q < 4; q++) { s0 += r0[q*256]; s1 += r1[q*256]; }
            float th0 = tanh_fast(s0 + bia);
            float th1 = tanh_fast(s1 + bia);
            hzP += DTc * (th0 - ga_*hyP - ep*hzP);  hyP += DTc * hzP;
            hzQ += DTc * (th1 - ga_*hyQ - ep*hzQ);  hyQ += DTc * hzQ;

            // own slice + x(t+1) into vbS[cur]
            float* vh = vbS + cur*VB_STRIDE_F + (c0 + col)*4;
            vh[bh]     = hyP;
            vh[bh + 2] = hyQ;
            float* vx = vbS + cur*VB_STRIDE_F + (512 + col)*4;
            vx[bh]     = xnP;
            vx[bh + 2] = xnQ;
        }
        asm volatile("bar.sync %0, 128;" :: "r"(barid) : "memory");

        // ---- push own 1KB slice to 7 peers (lanes 0..6 of group warp 0, parallel)
        if (t < Tn - 1 && gtid < 7) {
            asm volatile("fence.proxy.async.shared::cta;" ::: "memory");
            uint32_t off = (uint32_t)(cur*VB_BUF_BYTES + c0*16);
            dsmem_push(dstV + off, sbase + vbOff + off, SLICE_BYTES, cur ? dstM1 : dstM0);
        }

        // ---- deferred global stores
        {
            size_t oP = ((size_t)(b0 + 4*g + bh) * Tn + t) * Hn + hg;
            out[oP]                       = hyP;
            out[oP + (size_t)2 * Tn * Hn] = hyQ;
            if (t == Tn - 1 && writeFinal) {
                out[BTH + (size_t)(b0 + 4*g + bh)     * Hn + hg] = hyP;
                out[BTH + (size_t)(b0 + 4*g + bh + 2) * Hn + hg] = hyQ;
            }
        }
    }

    asm volatile("barrier.cluster.arrive.aligned;" ::: "memory");
    asm volatile("barrier.cluster.wait.aligned;"   ::: "memory");
}

extern "C" void kernel_launch(void* const* d_in, const int* in_sizes, int n_in,
                              void* d_out, int out_size) {
    const float* x    = (const float*)d_in[0];
    const float* x2h  = (const float*)d_in[1];
    const float* h2h  = (const float*)d_in[2];
    const float* bias = (const float*)d_in[3];
    const float* gam  = (const float*)d_in[4];
    const float* eps  = (const float*)d_in[5];
    float* out = (float*)d_out;
    (void)in_sizes; (void)n_in;

    cudaFuncSetAttribute(ron_kernel, cudaFuncAttributeMaxDynamicSharedMemorySize, SMEM_BYTES);
    ron_kernel<<<128, NT, SMEM_BYTES>>>(x, x2h, h2h, bias, gam, eps, out, (long long)out_size);
}